// round 4
// baseline (speedup 1.0000x reference)
#include <cuda_runtime.h>
#include <math.h>

#define B_   32
#define NN   1024
#define FIN  512
#define H1_  256
#define H2_  128

typedef unsigned long long ull;

// ---------------- scratch (device globals; no allocation allowed) ----------
__device__ float d_h1[B_ * NN * H1_];
__device__ float d_g1[B_ * NN * H1_];
__device__ float d_h2[B_ * NN * H2_];
__device__ float d_el[B_ * NN];
__device__ float d_er[B_ * NN];
__device__ float d_stat[B_ * 2];
__device__ float d_gv[B_ * NN];

__device__ __forceinline__ ull dup2(float x) {
    ull d;
    unsigned u = __float_as_uint(x);
    asm("mov.b64 %0, {%1, %1};" : "=l"(d) : "r"(u));
    return d;
}
__device__ __forceinline__ void fma2(ull& acc, ull a, ull b) {
    asm("fma.rn.f32x2 %0, %1, %2, %0;" : "+l"(acc) : "l"(a), "l"(b));
}
__device__ __forceinline__ void unpack2(ull v, float& lo, float& hi) {
    unsigned a, b;
    asm("mov.b64 {%0, %1}, %2;" : "=r"(a), "=r"(b) : "l"(v));
    lo = __uint_as_float(a);
    hi = __uint_as_float(b);
}
__device__ __forceinline__ ull pack2(float lo, float hi) {
    ull d;
    asm("mov.b64 %0, {%1, %2};" : "=l"(d) : "r"(__float_as_uint(lo)), "r"(__float_as_uint(hi)));
    return d;
}
__device__ __forceinline__ float attf(float x, float mn, float kk) {
    float lr = x >= 0.f ? x : 0.01f * x;
    return 1.f / (1.f + __expf(-(fmaf(lr - mn, kk, -20.f))));
}

// ---------------- warp-tiled packed-f32x2 SGEMM, double-buffered -------------
// C[M,N] = A[M,K] @ B[K,N]. Block tile 128x128, BK=16, 256 threads, 1 CTA/SM.
// Warps 4(row)x2(col); lanes 4(row)x8(col); per-thread 8x8 (32 f32x2 accs).
// MODE: 0 = A from global; 1 = A = att(el,er,stat) on the fly;
//       2 = like 1 but also writes the att tile to attOut (requires gridDim.x==1).
// EPI:  0 = none, 1 = ELU.
template <int MODE, int EPI>
__global__ void __launch_bounds__(256, 1)
sgemm_k(const float* __restrict__ A, const float* __restrict__ Bm,
        float* __restrict__ C, int N, int K,
        long long sA, long long sB, long long sC,
        const float* __restrict__ el, const float* __restrict__ er,
        const float* __restrict__ stat, float* __restrict__ attOut)
{
    __shared__ ull   As[2][16][128];   // A pre-duplicated {a,a}: 32 KB
    __shared__ float Bs[2][16][128];   // 16 KB

    const int bz = blockIdx.z;
    if (MODE == 0) A += (long long)bz * sA;
    Bm += (long long)bz * sB;
    C  += (long long)bz * sC;

    const int m0 = blockIdx.y * 128;
    const int n0 = blockIdx.x * 128;
    const int tid  = threadIdx.x;
    const int warp = tid >> 5, lane = tid & 31;
    const int mb = (warp >> 1) * 32 + (lane >> 3) * 8;
    const int nb = (warp & 1) * 64 + (lane & 7) * 8;

    // producer indices
    const int arow = tid >> 1;          // 0..127
    const int akq  = (tid & 1) * 8;     // k offset 0 or 8
    const int brow = tid >> 4;          // 0..15
    const int bcol = (tid & 15) * 8;    // 0..120

    float elv = 0.f, mn = 0.f, kk = 0.f;
    if (MODE != 0) {
        elv = el[bz * NN + m0 + arow];
        mn  = stat[bz * 2 + 0];
        kk  = stat[bz * 2 + 1];
    }

    ull acc[8][4] = {};
    float4 pa0, pa1, pb0, pb1;

    auto produce = [&](int k0) {
        if (MODE == 0) {
            const float* Ap = &A[(long long)(m0 + arow) * K + k0 + akq];
            pa0 = *(const float4*)Ap;
            pa1 = *(const float4*)(Ap + 4);
        } else {
            const float* erp = &er[bz * NN + k0 + akq];
            float4 e0 = *(const float4*)erp;
            float4 e1 = *(const float4*)(erp + 4);
            pa0.x = attf(elv + e0.x, mn, kk);
            pa0.y = attf(elv + e0.y, mn, kk);
            pa0.z = attf(elv + e0.z, mn, kk);
            pa0.w = attf(elv + e0.w, mn, kk);
            pa1.x = attf(elv + e1.x, mn, kk);
            pa1.y = attf(elv + e1.y, mn, kk);
            pa1.z = attf(elv + e1.z, mn, kk);
            pa1.w = attf(elv + e1.w, mn, kk);
            if (MODE == 2) {
                float* op = &attOut[(long long)bz * NN * NN +
                                    (long long)(m0 + arow) * NN + k0 + akq];
                *(float4*)op       = pa0;
                *(float4*)(op + 4) = pa1;
            }
        }
        const float* Bp = &Bm[(long long)(k0 + brow) * N + n0 + bcol];
        pb0 = *(const float4*)Bp;
        pb1 = *(const float4*)(Bp + 4);
    };

    auto store_smem = [&](int buf) {
        As[buf][akq + 0][arow] = dup2(pa0.x);
        As[buf][akq + 1][arow] = dup2(pa0.y);
        As[buf][akq + 2][arow] = dup2(pa0.z);
        As[buf][akq + 3][arow] = dup2(pa0.w);
        As[buf][akq + 4][arow] = dup2(pa1.x);
        As[buf][akq + 5][arow] = dup2(pa1.y);
        As[buf][akq + 6][arow] = dup2(pa1.z);
        As[buf][akq + 7][arow] = dup2(pa1.w);
        *(float4*)&Bs[buf][brow][bcol]     = pb0;
        *(float4*)&Bs[buf][brow][bcol + 4] = pb1;
    };

    auto compute16 = [&](int buf) {
#pragma unroll
        for (int k = 0; k < 16; k++) {
            ulonglong2 a01 = *(const ulonglong2*)&As[buf][k][mb + 0];
            ulonglong2 a23 = *(const ulonglong2*)&As[buf][k][mb + 2];
            ulonglong2 a45 = *(const ulonglong2*)&As[buf][k][mb + 4];
            ulonglong2 a67 = *(const ulonglong2*)&As[buf][k][mb + 6];
            ulonglong2 bq0 = *(const ulonglong2*)&Bs[buf][k][nb];
            ulonglong2 bq1 = *(const ulonglong2*)&Bs[buf][k][nb + 4];
            ull av[8] = {a01.x, a01.y, a23.x, a23.y, a45.x, a45.y, a67.x, a67.y};
            ull bv[4] = {bq0.x, bq0.y, bq1.x, bq1.y};
#pragma unroll
            for (int i = 0; i < 8; i++) {
#pragma unroll
                for (int j = 0; j < 4; j++) fma2(acc[i][j], av[i], bv[j]);
            }
        }
    };

    // ---- pipelined main loop: one barrier per chunk ----
    const int nChunks = K >> 4;
    produce(0);
    store_smem(0);
    __syncthreads();
    int buf = 0;
    for (int c = 1; c < nChunks; c++) {
        produce(c << 4);         // LDG issued before compute -> latency hidden
        compute16(buf);
        store_smem(buf ^ 1);
        __syncthreads();
        buf ^= 1;
    }
    compute16(buf);

    // ---- epilogue ----
#pragma unroll
    for (int i = 0; i < 8; i++) {
        const int m = m0 + mb + i;
        float* Crow = &C[(long long)m * N + n0 + nb];
        if (EPI == 1) {
#pragma unroll
            for (int j = 0; j < 4; j++) {
                float lo, hi;
                unpack2(acc[i][j], lo, hi);
                lo = lo > 0.f ? lo : (__expf(lo) - 1.f);
                hi = hi > 0.f ? hi : (__expf(hi) - 1.f);
                acc[i][j] = pack2(lo, hi);
            }
        }
        ulonglong2 v0; v0.x = acc[i][0]; v0.y = acc[i][1];
        ulonglong2 v1; v1.x = acc[i][2]; v1.y = acc[i][3];
        *(ulonglong2*)(Crow)     = v0;
        *(ulonglong2*)(Crow + 4) = v1;
    }
}

// ---------------- per-row dual dot: el = h.aL, er = h.aR --------------------
__global__ void rowdot(const float* __restrict__ h, const float* __restrict__ a,
                       float* __restrict__ el, float* __restrict__ er, int Fo)
{
    const int row  = (blockIdx.x * blockDim.x + threadIdx.x) >> 5;
    const int lane = threadIdx.x & 31;
    const float* hp = h + (long long)row * Fo;
    float sl = 0.f, sr = 0.f;
    for (int c = lane; c < Fo; c += 32) {
        float v = hp[c];
        sl = fmaf(v, a[c], sl);
        sr = fmaf(v, a[Fo + c], sr);
    }
#pragma unroll
    for (int o = 16; o; o >>= 1) {
        sl += __shfl_xor_sync(0xFFFFFFFFu, sl, o);
        sr += __shfl_xor_sync(0xFFFFFFFFu, sr, o);
    }
    if (lane == 0) { el[row] = sl; er[row] = sr; }
}

// ---------------- per-batch min/max of separable e --------------------------
__global__ void minmax_stats(const float* __restrict__ el, const float* __restrict__ er,
                             float* __restrict__ stat)
{
    const int b = blockIdx.x;
    const int tid = threadIdx.x;
    float mnl = 1e30f, mxl = -1e30f, mnr = 1e30f, mxr = -1e30f;
    for (int i = tid; i < NN; i += 256) {
        float l = el[b * NN + i], r = er[b * NN + i];
        mnl = fminf(mnl, l); mxl = fmaxf(mxl, l);
        mnr = fminf(mnr, r); mxr = fmaxf(mxr, r);
    }
#pragma unroll
    for (int o = 16; o; o >>= 1) {
        mnl = fminf(mnl, __shfl_xor_sync(0xFFFFFFFFu, mnl, o));
        mxl = fmaxf(mxl, __shfl_xor_sync(0xFFFFFFFFu, mxl, o));
        mnr = fminf(mnr, __shfl_xor_sync(0xFFFFFFFFu, mnr, o));
        mxr = fmaxf(mxr, __shfl_xor_sync(0xFFFFFFFFu, mxr, o));
    }
    __shared__ float s[4][8];
    const int w = tid >> 5, lane = tid & 31;
    if (lane == 0) { s[0][w] = mnl; s[1][w] = mxl; s[2][w] = mnr; s[3][w] = mxr; }
    __syncthreads();
    if (tid == 0) {
        float a0 = s[0][0], a1 = s[1][0], a2 = s[2][0], a3 = s[3][0];
#pragma unroll
        for (int i = 1; i < 8; i++) {
            a0 = fminf(a0, s[0][i]); a1 = fmaxf(a1, s[1][i]);
            a2 = fminf(a2, s[2][i]); a3 = fmaxf(a3, s[3][i]);
        }
        float lo = a0 + a2, hi = a1 + a3;
        float mn = lo >= 0.f ? lo : 0.01f * lo;
        float mx = hi >= 0.f ? hi : 0.01f * hi;
        stat[b * 2 + 0] = mn;
        stat[b * 2 + 1] = 30.f / (mx - mn);
    }
}

// ---------------- gv = g2 @ Wg ----------------------------------------------
__global__ void gv_kernel(const float* __restrict__ g2, const float* __restrict__ Wg,
                          float* __restrict__ gv)
{
    const int row  = (blockIdx.x * blockDim.x + threadIdx.x) >> 5;
    const int lane = threadIdx.x & 31;
    const float* gp = g2 + (long long)row * H2_;
    float s = fmaf(gp[lane], Wg[lane], gp[lane + 32] * Wg[lane + 32]);
    s = fmaf(gp[lane + 64], Wg[lane + 64], s);
    s = fmaf(gp[lane + 96], Wg[lane + 96], s);
#pragma unroll
    for (int o = 16; o; o >>= 1) s += __shfl_xor_sync(0xFFFFFFFFu, s, o);
    if (lane == 0) gv[row] = s;
}

// ---------------- out = leaky(fc2 @ gv + bg) ----------------------------------
__global__ void z_kernel(const float* __restrict__ fc2, const float* __restrict__ gv,
                         const float* __restrict__ bg, float* __restrict__ out)
{
    const int row  = (blockIdx.x * blockDim.x + threadIdx.x) >> 5;
    const int lane = threadIdx.x & 31;
    const int b = row >> 10;
    const float* fr = fc2 + (long long)row * NN;
    const float* gr = gv + b * NN;
    float s = 0.f;
#pragma unroll
    for (int j = lane * 4; j < NN; j += 128) {
        float4 f = *(const float4*)&fr[j];
        float4 g = *(const float4*)&gr[j];
        s = fmaf(f.x, g.x, s); s = fmaf(f.y, g.y, s);
        s = fmaf(f.z, g.z, s); s = fmaf(f.w, g.w, s);
    }
#pragma unroll
    for (int o = 16; o; o >>= 1) s += __shfl_xor_sync(0xFFFFFFFFu, s, o);
    if (lane == 0) {
        float z = s + bg[0];
        out[row] = z >= 0.f ? z : 0.01f * z;
    }
}

// ---------------------------------------------------------------------------
static float* sym_f(const void* s)
{
    void* p = nullptr;
    cudaGetSymbolAddress(&p, s);
    return (float*)p;
}

extern "C" void kernel_launch(void* const* d_in, const int* in_sizes, int n_in,
                              void* d_out, int out_size)
{
    const float* x  = (const float*)d_in[0];
    const float* W1 = (const float*)d_in[2];
    const float* a1 = (const float*)d_in[3];
    const float* W2 = (const float*)d_in[4];
    const float* a2 = (const float*)d_in[5];
    const float* Wg = (const float*)d_in[6];
    const float* bg = (const float*)d_in[7];

    float* out = (float*)d_out;
    float* fc2 = out + (long long)B_ * NN;
    float* g2  = fc2 + (long long)B_ * NN * NN;

    float* h1   = sym_f(d_h1);
    float* g1   = sym_f(d_g1);
    float* h2   = sym_f(d_h2);
    float* el   = sym_f(d_el);
    float* er   = sym_f(d_er);
    float* stat = sym_f(d_stat);
    float* gv   = sym_f(d_gv);

    const dim3 blk(256);
    const int rowsTot = B_ * NN;           // 32768

    // ===== Layer 1 =====
    sgemm_k<0, 0><<<dim3(H1_ / 128, rowsTot / 128, 1), blk>>>(
        x, W1, h1, H1_, FIN, 0, 0, 0, nullptr, nullptr, nullptr, nullptr);
    rowdot<<<rowsTot / 8, 256>>>(h1, a1, el, er, H1_);
    minmax_stats<<<B_, 256>>>(el, er, stat);
    sgemm_k<1, 1><<<dim3(H1_ / 128, NN / 128, B_), blk>>>(
        nullptr, h1, g1, H1_, NN,
        0, (long long)NN * H1_, (long long)NN * H1_, el, er, stat, nullptr);

    // ===== Layer 2 =====
    sgemm_k<0, 0><<<dim3(H2_ / 128, rowsTot / 128, 1), blk>>>(
        g1, W2, h2, H2_, H1_, 0, 0, 0, nullptr, nullptr, nullptr, nullptr);
    rowdot<<<rowsTot / 8, 256>>>(h2, a2, el, er, H2_);
    minmax_stats<<<B_, 256>>>(el, er, stat);
    sgemm_k<2, 0><<<dim3(H2_ / 128, NN / 128, B_), blk>>>(
        nullptr, h2, g2, H2_, NN,
        0, (long long)NN * H2_, (long long)NN * H2_, el, er, stat, fc2);

    // ===== Head: out = leaky(fc2 @ (g2 @ Wg) + bg) =====
    gv_kernel<<<rowsTot / 8, 256>>>(g2, Wg, gv);
    z_kernel<<<rowsTot / 8, 256>>>(fc2, gv, bg, out);
}

// round 7
// speedup vs baseline: 1.7740x; 1.7740x over previous
#include <cuda_runtime.h>
#include <cuda_bf16.h>
#include <math.h>
#include <stdint.h>

#define B_   32
#define NN   1024
#define FIN  512
#define H1_  256
#define H2_  128

// ---------------- scratch (device globals; no allocation allowed) ----------
__device__ float d_h1[B_ * NN * H1_];
__device__ float d_g1[B_ * NN * H1_];
__device__ float d_h2[B_ * NN * H2_];
__device__ float d_el[B_ * NN];
__device__ float d_er[B_ * NN];
__device__ float d_stat[B_ * 2];
__device__ float d_gv[B_ * NN];
// transposed + bf16-split B operands ([N][K] layout)
__device__ __nv_bfloat16 d_ht1_hi[B_ * H1_ * NN];
__device__ __nv_bfloat16 d_ht1_lo[B_ * H1_ * NN];
__device__ __nv_bfloat16 d_ht2_hi[B_ * H2_ * NN];
__device__ __nv_bfloat16 d_ht2_lo[B_ * H2_ * NN];
__device__ __nv_bfloat16 d_wt1_hi[H1_ * FIN];
__device__ __nv_bfloat16 d_wt1_lo[H1_ * FIN];
__device__ __nv_bfloat16 d_wt2_hi[H2_ * H1_];
__device__ __nv_bfloat16 d_wt2_lo[H2_ * H1_];

__device__ __forceinline__ uint32_t smem_u32(const void* p) {
    return (uint32_t)__cvta_generic_to_shared(p);
}
__device__ __forceinline__ uint32_t sw128(uint32_t off) {
    return off ^ ((off >> 3) & 0x70);
}
__device__ __forceinline__ float attf(float x, float mn, float kk) {
    float lr = x >= 0.f ? x : 0.01f * x;
    return 1.f / (1.f + __expf(-(fmaf(lr - mn, kk, -20.f))));
}
__device__ __forceinline__ void ldx4(unsigned* r, uint32_t addr) {
    asm volatile("ldmatrix.sync.aligned.m8n8.x4.shared.b16 {%0,%1,%2,%3}, [%4];"
                 : "=r"(r[0]), "=r"(r[1]), "=r"(r[2]), "=r"(r[3]) : "r"(addr));
}
__device__ __forceinline__ void ldx2(unsigned* r, uint32_t addr) {
    asm volatile("ldmatrix.sync.aligned.m8n8.x2.shared.b16 {%0,%1}, [%2];"
                 : "=r"(r[0]), "=r"(r[1]) : "r"(addr));
}
__device__ __forceinline__ void mma16816(float* c, const unsigned* a, const unsigned* b) {
    asm volatile(
        "mma.sync.aligned.m16n8k16.row.col.f32.bf16.bf16.f32 "
        "{%0,%1,%2,%3}, {%4,%5,%6,%7}, {%8,%9}, {%0,%1,%2,%3};"
        : "+f"(c[0]), "+f"(c[1]), "+f"(c[2]), "+f"(c[3])
        : "r"(a[0]), "r"(a[1]), "r"(a[2]), "r"(a[3]), "r"(b[0]), "r"(b[1]));
}

// ---------------- tensor-core GEMM: C[M,N] = A[M,K] @ Bt^T -------------------
// A: [M,K] fp32 (MODE 0) or att(el,er,stat) on the fly (MODE 1; MODE 2 also
// writes fp32 att to attOut — requires gridDim.x == 1). Bt: bf16 hi/lo [N][K].
// CTA tile 128x128, BK=64, 8 warps (2m x 4n), warp tile 64x32, m16n8k16.
// bf16x3: hi*hi + lo*hi + hi*lo. EPI: 0 none, 1 ELU.
template <int MODE, int EPI>
__global__ void __launch_bounds__(256, 1)
tc_gemm(const float* __restrict__ A,
        const __nv_bfloat16* __restrict__ Bhi, const __nv_bfloat16* __restrict__ Blo,
        float* __restrict__ C, int N, int K,
        long long sA, long long sBt, long long sC,
        const float* __restrict__ el, const float* __restrict__ er,
        const float* __restrict__ stat, float* __restrict__ attOut)
{
    extern __shared__ char smem[];
    // per buffer: A_hi 16K | A_lo 16K | B_hi 16K | B_lo 16K = 64K; two buffers
    constexpr int BUF = 65536;
    constexpr int OAH = 0, OAL = 16384, OBH = 32768, OBL = 49152;

    const int bz = blockIdx.z;
    if (MODE == 0) A += (long long)bz * sA;
    Bhi += (long long)bz * sBt;
    Blo += (long long)bz * sBt;
    C   += (long long)bz * sC;

    const int m0 = blockIdx.y * 128;
    const int n0 = blockIdx.x * 128;
    const int tid  = threadIdx.x;
    const int warp = tid >> 5, lane = tid & 31;
    const int mw = (warp >> 2) * 64;     // warp row base in tile
    const int nw = (warp & 3) * 32;      // warp col base in tile

    const uint32_t sb = smem_u32(smem);

    // A producer mapping: row = tid>>1 (0..127), 32-col half (tid&1)
    const int ar = tid >> 1;
    const int ac = (tid & 1) * 32;
    float elv = 0.f, mn = 0.f, kk = 0.f;
    if (MODE != 0) {
        elv = el[bz * NN + m0 + ar];
        mn  = stat[bz * 2 + 0];
        kk  = stat[bz * 2 + 1];
    }

    auto produce = [&](int c, int buf) {
        const int k0 = c << 6;
        char* base = smem + buf * BUF;
        // ---- A tile: 128 x 64 fp32 -> hi/lo bf16, swizzled ----
        float v[32];
        if (MODE == 0) {
            const float4* Ap = (const float4*)(A + (long long)(m0 + ar) * K + k0 + ac);
#pragma unroll
            for (int q = 0; q < 8; q++) {
                float4 f = Ap[q];
                v[q * 4 + 0] = f.x; v[q * 4 + 1] = f.y;
                v[q * 4 + 2] = f.z; v[q * 4 + 3] = f.w;
            }
        } else {
            const float4* Ep = (const float4*)(er + bz * NN + k0 + ac);
#pragma unroll
            for (int q = 0; q < 8; q++) {
                float4 f = Ep[q];
                v[q * 4 + 0] = attf(elv + f.x, mn, kk);
                v[q * 4 + 1] = attf(elv + f.y, mn, kk);
                v[q * 4 + 2] = attf(elv + f.z, mn, kk);
                v[q * 4 + 3] = attf(elv + f.w, mn, kk);
            }
            if (MODE == 2) {
                float4* Op = (float4*)(attOut + (long long)bz * NN * NN +
                                       (long long)(m0 + ar) * NN + k0 + ac);
#pragma unroll
                for (int q = 0; q < 8; q++)
                    Op[q] = make_float4(v[q * 4], v[q * 4 + 1], v[q * 4 + 2], v[q * 4 + 3]);
            }
        }
#pragma unroll
        for (int g = 0; g < 4; g++) {
            uint4 hq, lq;
            uint32_t* hw = (uint32_t*)&hq;
            uint32_t* lw = (uint32_t*)&lq;
#pragma unroll
            for (int e = 0; e < 4; e++) {
                float x0 = v[g * 8 + e * 2], x1 = v[g * 8 + e * 2 + 1];
                __nv_bfloat16 h0 = __float2bfloat16(x0), h1 = __float2bfloat16(x1);
                float r0 = x0 - __bfloat162float(h0);
                float r1 = x1 - __bfloat162float(h1);
                __nv_bfloat16 l0 = __float2bfloat16(r0), l1 = __float2bfloat16(r1);
                hw[e] = (uint32_t)__bfloat16_as_ushort(h0) |
                        ((uint32_t)__bfloat16_as_ushort(h1) << 16);
                lw[e] = (uint32_t)__bfloat16_as_ushort(l0) |
                        ((uint32_t)__bfloat16_as_ushort(l1) << 16);
            }
            uint32_t so = sw128(ar * 128 + ac * 2 + g * 16);
            *(uint4*)(base + OAH + so) = hq;
            *(uint4*)(base + OAL + so) = lq;
        }
        // ---- B tile: 128 rows(n) x 64 cols(k) bf16 = 8 granules/row ----
#pragma unroll
        for (int rep = 0; rep < 4; rep++) {
            int idx = tid + rep * 256;         // 0..1023 granules per plane
            int row = idx >> 3, q = idx & 7;
            uint4 hv = *(const uint4*)(Bhi + (long long)(n0 + row) * K + k0 + q * 8);
            uint4 lv = *(const uint4*)(Blo + (long long)(n0 + row) * K + k0 + q * 8);
            uint32_t so = sw128(row * 128 + q * 16);
            *(uint4*)(base + OBH + so) = hv;
            *(uint4*)(base + OBL + so) = lv;
        }
    };

    float acc[4][4][4] = {};

    auto consume = [&](int buf) {
        const uint32_t aH = sb + buf * BUF + OAH;
        const uint32_t aL = sb + buf * BUF + OAL;
        const uint32_t bH = sb + buf * BUF + OBH;
        const uint32_t bL = sb + buf * BUF + OBL;
        // ldmatrix lane offsets
        const uint32_t aRow = (lane & 15);
        const uint32_t aKof = (lane >> 4) * 16;
        const uint32_t bRow = (lane & 7);
        const uint32_t bKof = ((lane >> 3) & 1) * 16;
#pragma unroll
        for (int ks = 0; ks < 4; ks++) {
            const uint32_t kb = ks * 32;       // byte col of k0+ks*16
            unsigned ah[4][4], al[4][4], bh[4][2], bl[4][2];
#pragma unroll
            for (int mt = 0; mt < 4; mt++) {
                uint32_t off = sw128((mw + mt * 16 + aRow) * 128 + kb + aKof);
                ldx4(ah[mt], aH + off);
                ldx4(al[mt], aL + off);
            }
#pragma unroll
            for (int nt = 0; nt < 4; nt++) {
                uint32_t off = sw128((nw + nt * 8 + bRow) * 128 + kb + bKof);
                ldx2(bh[nt], bH + off);
                ldx2(bl[nt], bL + off);
            }
#pragma unroll
            for (int mt = 0; mt < 4; mt++) {
#pragma unroll
                for (int nt = 0; nt < 4; nt++) {
                    mma16816(acc[mt][nt], ah[mt], bh[nt]);
                    mma16816(acc[mt][nt], al[mt], bh[nt]);
                    mma16816(acc[mt][nt], ah[mt], bl[nt]);
                }
            }
        }
    };

    const int nCh = K >> 6;
    produce(0, 0);
    __syncthreads();
    int buf = 0;
    for (int c = 0; c < nCh; c++) {
        if (c + 1 < nCh) produce(c + 1, buf ^ 1);
        consume(buf);
        __syncthreads();
        buf ^= 1;
    }

    // ---- epilogue: fragment -> global ----
    const int r0 = lane >> 2;
    const int cc = (lane & 3) * 2;
#pragma unroll
    for (int mt = 0; mt < 4; mt++) {
#pragma unroll
        for (int nt = 0; nt < 4; nt++) {
            float* a4 = acc[mt][nt];
            if (EPI == 1) {
#pragma unroll
                for (int e = 0; e < 4; e++)
                    a4[e] = a4[e] > 0.f ? a4[e] : (__expf(a4[e]) - 1.f);
            }
            const int col = n0 + nw + nt * 8 + cc;
            const int row = m0 + mw + mt * 16 + r0;
            *(float2*)&C[(long long)row * N + col]       = make_float2(a4[0], a4[1]);
            *(float2*)&C[(long long)(row + 8) * N + col] = make_float2(a4[2], a4[3]);
        }
    }
}

// ---------------- transpose + bf16 split: dst[c][r] = split(src[r][c]) ------
__global__ void prepT(const float* __restrict__ src, __nv_bfloat16* __restrict__ dhi,
                      __nv_bfloat16* __restrict__ dlo, int R, int Cc,
                      long long sS, long long sD)
{
    __shared__ float t[32][33];
    const int bz = blockIdx.z;
    src += (long long)bz * sS;
    dhi += (long long)bz * sD;
    dlo += (long long)bz * sD;
    const int c0 = blockIdx.x * 32;
    const int r0 = blockIdx.y * 32;
    const int tx = threadIdx.x, ty = threadIdx.y;
#pragma unroll
    for (int i = ty; i < 32; i += 8)
        t[i][tx] = src[(long long)(r0 + i) * Cc + c0 + tx];
    __syncthreads();
#pragma unroll
    for (int i = ty; i < 32; i += 8) {
        float v = t[tx][i];
        __nv_bfloat16 h = __float2bfloat16(v);
        float rr = v - __bfloat162float(h);
        dhi[(long long)(c0 + i) * R + r0 + tx] = h;
        dlo[(long long)(c0 + i) * R + r0 + tx] = __float2bfloat16(rr);
    }
}

// ---------------- per-row dual dot: el = h.aL, er = h.aR --------------------
__global__ void rowdot(const float* __restrict__ h, const float* __restrict__ a,
                       float* __restrict__ el, float* __restrict__ er, int Fo)
{
    const int row  = (blockIdx.x * blockDim.x + threadIdx.x) >> 5;
    const int lane = threadIdx.x & 31;
    const float* hp = h + (long long)row * Fo;
    float sl = 0.f, sr = 0.f;
    for (int c = lane; c < Fo; c += 32) {
        float v = hp[c];
        sl = fmaf(v, a[c], sl);
        sr = fmaf(v, a[Fo + c], sr);
    }
#pragma unroll
    for (int o = 16; o; o >>= 1) {
        sl += __shfl_xor_sync(0xFFFFFFFFu, sl, o);
        sr += __shfl_xor_sync(0xFFFFFFFFu, sr, o);
    }
    if (lane == 0) { el[row] = sl; er[row] = sr; }
}

// ---------------- per-batch min/max of separable e --------------------------
__global__ void minmax_stats(const float* __restrict__ el, const float* __restrict__ er,
                             float* __restrict__ stat)
{
    const int b = blockIdx.x;
    const int tid = threadIdx.x;
    float mnl = 1e30f, mxl = -1e30f, mnr = 1e30f, mxr = -1e30f;
    for (int i = tid; i < NN; i += 256) {
        float l = el[b * NN + i], r = er[b * NN + i];
        mnl = fminf(mnl, l); mxl = fmaxf(mxl, l);
        mnr = fminf(mnr, r); mxr = fmaxf(mxr, r);
    }
#pragma unroll
    for (int o = 16; o; o >>= 1) {
        mnl = fminf(mnl, __shfl_xor_sync(0xFFFFFFFFu, mnl, o));
        mxl = fmaxf(mxl, __shfl_xor_sync(0xFFFFFFFFu, mxl, o));
        mnr = fminf(mnr, __shfl_xor_sync(0xFFFFFFFFu, mnr, o));
        mxr = fmaxf(mxr, __shfl_xor_sync(0xFFFFFFFFu, mxr, o));
    }
    __shared__ float s[4][8];
    const int w = tid >> 5, lane = tid & 31;
    if (lane == 0) { s[0][w] = mnl; s[1][w] = mxl; s[2][w] = mnr; s[3][w] = mxr; }
    __syncthreads();
    if (tid == 0) {
        float a0 = s[0][0], a1 = s[1][0], a2 = s[2][0], a3 = s[3][0];
#pragma unroll
        for (int i = 1; i < 8; i++) {
            a0 = fminf(a0, s[0][i]); a1 = fmaxf(a1, s[1][i]);
            a2 = fminf(a2, s[2][i]); a3 = fmaxf(a3, s[3][i]);
        }
        float lo = a0 + a2, hi = a1 + a3;
        float mn = lo >= 0.f ? lo : 0.01f * lo;
        float mx = hi >= 0.f ? hi : 0.01f * hi;
        stat[b * 2 + 0] = mn;
        stat[b * 2 + 1] = 30.f / (mx - mn);
    }
}

// ---------------- gv = g2 @ Wg ----------------------------------------------
__global__ void gv_kernel(const float* __restrict__ g2, const float* __restrict__ Wg,
                          float* __restrict__ gv)
{
    const int row  = (blockIdx.x * blockDim.x + threadIdx.x) >> 5;
    const int lane = threadIdx.x & 31;
    const float* gp = g2 + (long long)row * H2_;
    float s = fmaf(gp[lane], Wg[lane], gp[lane + 32] * Wg[lane + 32]);
    s = fmaf(gp[lane + 64], Wg[lane + 64], s);
    s = fmaf(gp[lane + 96], Wg[lane + 96], s);
#pragma unroll
    for (int o = 16; o; o >>= 1) s += __shfl_xor_sync(0xFFFFFFFFu, s, o);
    if (lane == 0) gv[row] = s;
}

// ---------------- out = leaky(fc2 @ gv + bg) ----------------------------------
__global__ void z_kernel(const float* __restrict__ fc2, const float* __restrict__ gv,
                         const float* __restrict__ bg, float* __restrict__ out)
{
    const int row  = (blockIdx.x * blockDim.x + threadIdx.x) >> 5;
    const int lane = threadIdx.x & 31;
    const int b = row >> 10;
    const float* fr = fc2 + (long long)row * NN;
    const float* gr = gv + b * NN;
    float s = 0.f;
#pragma unroll
    for (int j = lane * 4; j < NN; j += 128) {
        float4 f = *(const float4*)&fr[j];
        float4 g = *(const float4*)&gr[j];
        s = fmaf(f.x, g.x, s); s = fmaf(f.y, g.y, s);
        s = fmaf(f.z, g.z, s); s = fmaf(f.w, g.w, s);
    }
#pragma unroll
    for (int o = 16; o; o >>= 1) s += __shfl_xor_sync(0xFFFFFFFFu, s, o);
    if (lane == 0) {
        float z = s + bg[0];
        out[row] = z >= 0.f ? z : 0.01f * z;
    }
}

// ---------------------------------------------------------------------------
template <typename T>
static T* sym_p(const void* s)
{
    void* p = nullptr;
    cudaGetSymbolAddress(&p, s);
    return (T*)p;
}

extern "C" void kernel_launch(void* const* d_in, const int* in_sizes, int n_in,
                              void* d_out, int out_size)
{
    const float* x  = (const float*)d_in[0];
    const float* W1 = (const float*)d_in[2];
    const float* a1 = (const float*)d_in[3];
    const float* W2 = (const float*)d_in[4];
    const float* a2 = (const float*)d_in[5];
    const float* Wg = (const float*)d_in[6];
    const float* bg = (const float*)d_in[7];

    float* out = (float*)d_out;
    float* fc2 = out + (long long)B_ * NN;
    float* g2  = fc2 + (long long)B_ * NN * NN;

    float* h1   = sym_p<float>(d_h1);
    float* g1   = sym_p<float>(d_g1);
    float* h2   = sym_p<float>(d_h2);
    float* el   = sym_p<float>(d_el);
    float* er   = sym_p<float>(d_er);
    float* stat = sym_p<float>(d_stat);
    float* gv   = sym_p<float>(d_gv);
    __nv_bfloat16* ht1h = sym_p<__nv_bfloat16>(d_ht1_hi);
    __nv_bfloat16* ht1l = sym_p<__nv_bfloat16>(d_ht1_lo);
    __nv_bfloat16* ht2h = sym_p<__nv_bfloat16>(d_ht2_hi);
    __nv_bfloat16* ht2l = sym_p<__nv_bfloat16>(d_ht2_lo);
    __nv_bfloat16* wt1h = sym_p<__nv_bfloat16>(d_wt1_hi);
    __nv_bfloat16* wt1l = sym_p<__nv_bfloat16>(d_wt1_lo);
    __nv_bfloat16* wt2h = sym_p<__nv_bfloat16>(d_wt2_hi);
    __nv_bfloat16* wt2l = sym_p<__nv_bfloat16>(d_wt2_lo);

    const int SMB = 2 * 65536;   // 128 KB dynamic smem
    cudaFuncSetAttribute(tc_gemm<0, 0>, cudaFuncAttributeMaxDynamicSharedMemorySize, SMB);
    cudaFuncSetAttribute(tc_gemm<1, 1>, cudaFuncAttributeMaxDynamicSharedMemorySize, SMB);
    cudaFuncSetAttribute(tc_gemm<2, 0>, cudaFuncAttributeMaxDynamicSharedMemorySize, SMB);

    const int rowsTot = B_ * NN;              // 32768
    const dim3 tp(32, 8);

    // ===== weight preps (tiny) =====
    prepT<<<dim3(H1_ / 32, FIN / 32, 1), tp>>>(W1, wt1h, wt1l, FIN, H1_, 0, 0);
    prepT<<<dim3(H2_ / 32, H1_ / 32, 1), tp>>>(W2, wt2h, wt2l, H1_, H2_, 0, 0);

    // ===== Layer 1 =====
    // h1 = x @ W1
    tc_gemm<0, 0><<<dim3(H1_ / 128, rowsTot / 128, 1), 256, SMB>>>(
        x, wt1h, wt1l, h1, H1_, FIN, 0, 0, 0, nullptr, nullptr, nullptr, nullptr);
    rowdot<<<rowsTot / 8, 256>>>(h1, a1, el, er, H1_);
    minmax_stats<<<B_, 256>>>(el, er, stat);
    prepT<<<dim3(H1_ / 32, NN / 32, B_), tp>>>(
        h1, ht1h, ht1l, NN, H1_, (long long)NN * H1_, (long long)H1_ * NN);
    // g1 = elu(att1 @ h1), att1 on the fly
    tc_gemm<1, 1><<<dim3(H1_ / 128, NN / 128, B_), 256, SMB>>>(
        nullptr, ht1h, ht1l, g1, H1_, NN,
        0, (long long)H1_ * NN, (long long)NN * H1_, el, er, stat, nullptr);

    // ===== Layer 2 =====
    tc_gemm<0, 0><<<dim3(H2_ / 128, rowsTot / 128, 1), 256, SMB>>>(
        g1, wt2h, wt2l, h2, H2_, H1_, 0, 0, 0, nullptr, nullptr, nullptr, nullptr);
    rowdot<<<rowsTot / 8, 256>>>(h2, a2, el, er, H2_);
    minmax_stats<<<B_, 256>>>(el, er, stat);
    prepT<<<dim3(H2_ / 32, NN / 32, B_), tp>>>(
        h2, ht2h, ht2l, NN, H2_, (long long)NN * H2_, (long long)H2_ * NN);
    // g2 = fc2 @ h2; fc2 written on the fly (gridDim.x == 1)
    tc_gemm<2, 0><<<dim3(H2_ / 128, NN / 128, B_), 256, SMB>>>(
        nullptr, ht2h, ht2l, g2, H2_, NN,
        0, (long long)H2_ * NN, (long long)NN * H2_, el, er, stat, fc2);

    // ===== Head: out = leaky(fc2 @ (g2 @ Wg) + bg) =====
    gv_kernel<<<rowsTot / 8, 256>>>(g2, Wg, gv);
    z_kernel<<<rowsTot / 8, 256>>>(fc2, gv, bg, out);
}

// round 8
// speedup vs baseline: 2.0876x; 1.1767x over previous
#include <cuda_runtime.h>
#include <cuda_bf16.h>
#include <math.h>
#include <stdint.h>

#define B_   32
#define NN   1024
#define FIN  512
#define H1_  256
#define H2_  128

// ---------------- scratch (device globals; no allocation allowed) ----------
__device__ float d_h1[B_ * NN * H1_];
__device__ float d_g1[B_ * NN * H1_];
__device__ float d_h2[B_ * NN * H2_];
__device__ float d_el[B_ * NN];
__device__ float d_er[B_ * NN];
__device__ float d_stat[B_ * 2];
__device__ float d_gv[B_ * NN];
// transposed + bf16-split B operands ([N][K] layout)
__device__ __nv_bfloat16 d_ht1_hi[B_ * H1_ * NN];
__device__ __nv_bfloat16 d_ht1_lo[B_ * H1_ * NN];
__device__ __nv_bfloat16 d_ht2_hi[B_ * H2_ * NN];
__device__ __nv_bfloat16 d_ht2_lo[B_ * H2_ * NN];
__device__ __nv_bfloat16 d_wt1_hi[H1_ * FIN];
__device__ __nv_bfloat16 d_wt1_lo[H1_ * FIN];
__device__ __nv_bfloat16 d_wt2_hi[H2_ * H1_];
__device__ __nv_bfloat16 d_wt2_lo[H2_ * H1_];

__device__ __forceinline__ uint32_t smem_u32(const void* p) {
    return (uint32_t)__cvta_generic_to_shared(p);
}
__device__ __forceinline__ uint32_t sw128(uint32_t off) {
    return off ^ ((off >> 3) & 0x70);
}
__device__ __forceinline__ float attf(float x, float mn, float kk) {
    float lr = x >= 0.f ? x : 0.01f * x;
    return 1.f / (1.f + __expf(-(fmaf(lr - mn, kk, -20.f))));
}
__device__ __forceinline__ void ldx4(unsigned* r, uint32_t addr) {
    asm volatile("ldmatrix.sync.aligned.m8n8.x4.shared.b16 {%0,%1,%2,%3}, [%4];"
                 : "=r"(r[0]), "=r"(r[1]), "=r"(r[2]), "=r"(r[3]) : "r"(addr));
}
__device__ __forceinline__ void ldx2(unsigned* r, uint32_t addr) {
    asm volatile("ldmatrix.sync.aligned.m8n8.x2.shared.b16 {%0,%1}, [%2];"
                 : "=r"(r[0]), "=r"(r[1]) : "r"(addr));
}
__device__ __forceinline__ void mma16816(float* c, const unsigned* a, const unsigned* b) {
    asm volatile(
        "mma.sync.aligned.m16n8k16.row.col.f32.bf16.bf16.f32 "
        "{%0,%1,%2,%3}, {%4,%5,%6,%7}, {%8,%9}, {%0,%1,%2,%3};"
        : "+f"(c[0]), "+f"(c[1]), "+f"(c[2]), "+f"(c[3])
        : "r"(a[0]), "r"(a[1]), "r"(a[2]), "r"(a[3]), "r"(b[0]), "r"(b[1]));
}
__device__ __forceinline__ void cpasync16(uint32_t saddr, const void* gptr) {
    asm volatile("cp.async.cg.shared.global [%0], [%1], 16;"
                 :: "r"(saddr), "l"(gptr) : "memory");
}
#define CP_COMMIT() asm volatile("cp.async.commit_group;" ::: "memory")
#define CP_WAIT0()  asm volatile("cp.async.wait_group 0;" ::: "memory")

// ---------------- tensor-core GEMM: C[M,N] = A[M,K] @ Bt^T -------------------
// A: [M,K] fp32 (MODE 0) or att(el,er,stat) on the fly (MODE 1; MODE 2 also
// writes fp32 att to attOut — requires gridDim.x == 1). Bt: bf16 hi/lo [N][K].
// CTA tile 128x128, BK=64, 8 warps (2m x 4n), warp tile 64x32, m16n8k16.
// bf16x3: hi*hi + lo*hi + hi*lo. EPI: 0 none, 1 ELU.
// Pipeline: A reg-prefetch (LDG covered by consume), B via cp.async;
// only convert+STS exposed per chunk.
template <int MODE, int EPI>
__global__ void __launch_bounds__(256, 1)
tc_gemm(const float* __restrict__ A,
        const __nv_bfloat16* __restrict__ Bhi, const __nv_bfloat16* __restrict__ Blo,
        float* __restrict__ C, int N, int K,
        long long sA, long long sBt, long long sC,
        const float* __restrict__ el, const float* __restrict__ er,
        const float* __restrict__ stat, float* __restrict__ attOut)
{
    extern __shared__ char smem[];
    // per buffer: A_hi 16K | A_lo 16K | B_hi 16K | B_lo 16K = 64K; two buffers
    constexpr int BUF = 65536;
    constexpr int OAH = 0, OAL = 16384, OBH = 32768, OBL = 49152;

    const int bz = blockIdx.z;
    if (MODE == 0) A += (long long)bz * sA;
    Bhi += (long long)bz * sBt;
    Blo += (long long)bz * sBt;
    C   += (long long)bz * sC;

    const int m0 = blockIdx.y * 128;
    const int n0 = blockIdx.x * 128;
    const int tid  = threadIdx.x;
    const int warp = tid >> 5, lane = tid & 31;
    const int mw = (warp >> 2) * 64;     // warp row base in tile
    const int nw = (warp & 3) * 32;      // warp col base in tile

    const uint32_t sb = smem_u32(smem);

    // A producer mapping: row = tid>>1 (0..127), 32-col half (tid&1)
    const int ar = tid >> 1;
    const int ac = (tid & 1) * 32;
    float elv = 0.f, mn = 0.f, kk = 0.f;
    if (MODE != 0) {
        elv = el[bz * NN + m0 + ar];
        mn  = stat[bz * 2 + 0];
        kk  = stat[bz * 2 + 1];
    }

    float va[32];

    // ---- load A-source for chunk c into registers (pure LDG) ----
    auto produce_load = [&](int c) {
        const int k0 = c << 6;
        const float4* Sp = (MODE == 0)
            ? (const float4*)(A + (long long)(m0 + ar) * K + k0 + ac)
            : (const float4*)(er + bz * NN + k0 + ac);
#pragma unroll
        for (int q = 0; q < 8; q++) {
            float4 f = Sp[q];
            va[q * 4 + 0] = f.x; va[q * 4 + 1] = f.y;
            va[q * 4 + 2] = f.z; va[q * 4 + 3] = f.w;
        }
    };

    // ---- B planes straight to smem via cp.async ----
    auto produce_B = [&](int c, int buf) {
        const int k0 = c << 6;
        const uint32_t dH = sb + buf * BUF + OBH;
        const uint32_t dL = sb + buf * BUF + OBL;
#pragma unroll
        for (int rep = 0; rep < 4; rep++) {
            int idx = tid + rep * 256;         // 0..1023 granules per plane
            int row = idx >> 3, q = idx & 7;
            uint32_t so = sw128(row * 128 + q * 16);
            cpasync16(dH + so, Bhi + (long long)(n0 + row) * K + k0 + q * 8);
            cpasync16(dL + so, Blo + (long long)(n0 + row) * K + k0 + q * 8);
        }
        CP_COMMIT();
    };

    // ---- finish A: attf (MODE!=0), split to hi/lo, STS (+ STG att, MODE 2) --
    auto produce_store = [&](int c, int buf) {
        char* base = smem + buf * BUF;
        if (MODE != 0) {
#pragma unroll
            for (int e = 0; e < 32; e++) va[e] = attf(elv + va[e], mn, kk);
            if (MODE == 2) {
                const int k0 = c << 6;
                float4* Op = (float4*)(attOut + (long long)bz * NN * NN +
                                       (long long)(m0 + ar) * NN + k0 + ac);
#pragma unroll
                for (int q = 0; q < 8; q++)
                    Op[q] = make_float4(va[q * 4], va[q * 4 + 1], va[q * 4 + 2], va[q * 4 + 3]);
            }
        }
#pragma unroll
        for (int g = 0; g < 4; g++) {
            uint4 hq, lq;
            uint32_t* hw = (uint32_t*)&hq;
            uint32_t* lw = (uint32_t*)&lq;
#pragma unroll
            for (int e = 0; e < 4; e++) {
                float x0 = va[g * 8 + e * 2], x1 = va[g * 8 + e * 2 + 1];
                __nv_bfloat16 h0 = __float2bfloat16(x0), h1 = __float2bfloat16(x1);
                float r0 = x0 - __bfloat162float(h0);
                float r1 = x1 - __bfloat162float(h1);
                __nv_bfloat16 l0 = __float2bfloat16(r0), l1 = __float2bfloat16(r1);
                hw[e] = (uint32_t)__bfloat16_as_ushort(h0) |
                        ((uint32_t)__bfloat16_as_ushort(h1) << 16);
                lw[e] = (uint32_t)__bfloat16_as_ushort(l0) |
                        ((uint32_t)__bfloat16_as_ushort(l1) << 16);
            }
            uint32_t so = sw128(ar * 128 + ac * 2 + g * 16);
            *(uint4*)(base + OAH + so) = hq;
            *(uint4*)(base + OAL + so) = lq;
        }
    };

    float acc[4][4][4] = {};

    auto consume = [&](int buf) {
        const uint32_t aH = sb + buf * BUF + OAH;
        const uint32_t aL = sb + buf * BUF + OAL;
        const uint32_t bH = sb + buf * BUF + OBH;
        const uint32_t bL = sb + buf * BUF + OBL;
        const uint32_t aRow = (lane & 15);
        const uint32_t aKof = (lane >> 4) * 16;
        const uint32_t bRow = (lane & 7);
        const uint32_t bKof = ((lane >> 3) & 1) * 16;
#pragma unroll
        for (int ks = 0; ks < 4; ks++) {
            const uint32_t kb = ks * 32;       // byte col of k0+ks*16
            unsigned ah[4][4], al[4][4], bh[4][2], bl[4][2];
#pragma unroll
            for (int mt = 0; mt < 4; mt++) {
                uint32_t off = sw128((mw + mt * 16 + aRow) * 128 + kb + aKof);
                ldx4(ah[mt], aH + off);
                ldx4(al[mt], aL + off);
            }
#pragma unroll
            for (int nt = 0; nt < 4; nt++) {
                uint32_t off = sw128((nw + nt * 8 + bRow) * 128 + kb + bKof);
                ldx2(bh[nt], bH + off);
                ldx2(bl[nt], bL + off);
            }
#pragma unroll
            for (int mt = 0; mt < 4; mt++) {
#pragma unroll
                for (int nt = 0; nt < 4; nt++) {
                    mma16816(acc[mt][nt], ah[mt], bh[nt]);
                    mma16816(acc[mt][nt], al[mt], bh[nt]);
                    mma16816(acc[mt][nt], ah[mt], bl[nt]);
                }
            }
        }
    };

    const int nCh = K >> 6;
    // prologue
    produce_load(0);
    produce_B(0, 0);
    produce_store(0, 0);
    CP_WAIT0();
    __syncthreads();

    int buf = 0;
    for (int c = 0; c < nCh; c++) {
        const bool more = (c + 1 < nCh);
        if (more) {
            produce_load(c + 1);       // LDG issued; latency covered by consume
            produce_B(c + 1, buf ^ 1); // cp.async, off-thread
        }
        consume(buf);
        if (more) produce_store(c + 1, buf ^ 1);
        CP_WAIT0();
        __syncthreads();
        buf ^= 1;
    }

    // ---- epilogue: fragment -> global ----
    const int r0 = lane >> 2;
    const int cc = (lane & 3) * 2;
#pragma unroll
    for (int mt = 0; mt < 4; mt++) {
#pragma unroll
        for (int nt = 0; nt < 4; nt++) {
            float* a4 = acc[mt][nt];
            if (EPI == 1) {
#pragma unroll
                for (int e = 0; e < 4; e++)
                    a4[e] = a4[e] > 0.f ? a4[e] : (__expf(a4[e]) - 1.f);
            }
            const int col = n0 + nw + nt * 8 + cc;
            const int row = m0 + mw + mt * 16 + r0;
            *(float2*)&C[(long long)row * N + col]       = make_float2(a4[0], a4[1]);
            *(float2*)&C[(long long)(row + 8) * N + col] = make_float2(a4[2], a4[3]);
        }
    }
}

// ---------------- transpose + bf16 split: dst[c][r] = split(src[r][c]) ------
__global__ void prepT(const float* __restrict__ src, __nv_bfloat16* __restrict__ dhi,
                      __nv_bfloat16* __restrict__ dlo, int R, int Cc,
                      long long sS, long long sD)
{
    __shared__ float t[32][33];
    const int bz = blockIdx.z;
    src += (long long)bz * sS;
    dhi += (long long)bz * sD;
    dlo += (long long)bz * sD;
    const int c0 = blockIdx.x * 32;
    const int r0 = blockIdx.y * 32;
    const int tx = threadIdx.x, ty = threadIdx.y;
#pragma unroll
    for (int i = ty; i < 32; i += 8)
        t[i][tx] = src[(long long)(r0 + i) * Cc + c0 + tx];
    __syncthreads();
#pragma unroll
    for (int i = ty; i < 32; i += 8) {
        float v = t[tx][i];
        __nv_bfloat16 h = __float2bfloat16(v);
        float rr = v - __bfloat162float(h);
        dhi[(long long)(c0 + i) * R + r0 + tx] = h;
        dlo[(long long)(c0 + i) * R + r0 + tx] = __float2bfloat16(rr);
    }
}

// ---------------- per-row dual dot: el = h.aL, er = h.aR --------------------
__global__ void rowdot(const float* __restrict__ h, const float* __restrict__ a,
                       float* __restrict__ el, float* __restrict__ er, int Fo)
{
    const int row  = (blockIdx.x * blockDim.x + threadIdx.x) >> 5;
    const int lane = threadIdx.x & 31;
    const float* hp = h + (long long)row * Fo;
    float sl = 0.f, sr = 0.f;
    for (int c = lane; c < Fo; c += 32) {
        float v = hp[c];
        sl = fmaf(v, a[c], sl);
        sr = fmaf(v, a[Fo + c], sr);
    }
#pragma unroll
    for (int o = 16; o; o >>= 1) {
        sl += __shfl_xor_sync(0xFFFFFFFFu, sl, o);
        sr += __shfl_xor_sync(0xFFFFFFFFu, sr, o);
    }
    if (lane == 0) { el[row] = sl; er[row] = sr; }
}

// ---------------- per-batch min/max of separable e --------------------------
__global__ void minmax_stats(const float* __restrict__ el, const float* __restrict__ er,
                             float* __restrict__ stat)
{
    const int b = blockIdx.x;
    const int tid = threadIdx.x;
    float mnl = 1e30f, mxl = -1e30f, mnr = 1e30f, mxr = -1e30f;
    for (int i = tid; i < NN; i += 256) {
        float l = el[b * NN + i], r = er[b * NN + i];
        mnl = fminf(mnl, l); mxl = fmaxf(mxl, l);
        mnr = fminf(mnr, r); mxr = fmaxf(mxr, r);
    }
#pragma unroll
    for (int o = 16; o; o >>= 1) {
        mnl = fminf(mnl, __shfl_xor_sync(0xFFFFFFFFu, mnl, o));
        mxl = fmaxf(mxl, __shfl_xor_sync(0xFFFFFFFFu, mxl, o));
        mnr = fminf(mnr, __shfl_xor_sync(0xFFFFFFFFu, mnr, o));
        mxr = fmaxf(mxr, __shfl_xor_sync(0xFFFFFFFFu, mxr, o));
    }
    __shared__ float s[4][8];
    const int w = tid >> 5, lane = tid & 31;
    if (lane == 0) { s[0][w] = mnl; s[1][w] = mxl; s[2][w] = mnr; s[3][w] = mxr; }
    __syncthreads();
    if (tid == 0) {
        float a0 = s[0][0], a1 = s[1][0], a2 = s[2][0], a3 = s[3][0];
#pragma unroll
        for (int i = 1; i < 8; i++) {
            a0 = fminf(a0, s[0][i]); a1 = fmaxf(a1, s[1][i]);
            a2 = fminf(a2, s[2][i]); a3 = fmaxf(a3, s[3][i]);
        }
        float lo = a0 + a2, hi = a1 + a3;
        float mn = lo >= 0.f ? lo : 0.01f * lo;
        float mx = hi >= 0.f ? hi : 0.01f * hi;
        stat[b * 2 + 0] = mn;
        stat[b * 2 + 1] = 30.f / (mx - mn);
    }
}

// ---------------- gv = g2 @ Wg ----------------------------------------------
__global__ void gv_kernel(const float* __restrict__ g2, const float* __restrict__ Wg,
                          float* __restrict__ gv)
{
    const int row  = (blockIdx.x * blockDim.x + threadIdx.x) >> 5;
    const int lane = threadIdx.x & 31;
    const float* gp = g2 + (long long)row * H2_;
    float s = fmaf(gp[lane], Wg[lane], gp[lane + 32] * Wg[lane + 32]);
    s = fmaf(gp[lane + 64], Wg[lane + 64], s);
    s = fmaf(gp[lane + 96], Wg[lane + 96], s);
#pragma unroll
    for (int o = 16; o; o >>= 1) s += __shfl_xor_sync(0xFFFFFFFFu, s, o);
    if (lane == 0) gv[row] = s;
}

// ---------------- out = leaky(fc2 @ gv + bg) ----------------------------------
__global__ void z_kernel(const float* __restrict__ fc2, const float* __restrict__ gv,
                         const float* __restrict__ bg, float* __restrict__ out)
{
    const int row  = (blockIdx.x * blockDim.x + threadIdx.x) >> 5;
    const int lane = threadIdx.x & 31;
    const int b = row >> 10;
    const float* fr = fc2 + (long long)row * NN;
    const float* gr = gv + b * NN;
    float s = 0.f;
#pragma unroll
    for (int j = lane * 4; j < NN; j += 128) {
        float4 f = *(const float4*)&fr[j];
        float4 g = *(const float4*)&gr[j];
        s = fmaf(f.x, g.x, s); s = fmaf(f.y, g.y, s);
        s = fmaf(f.z, g.z, s); s = fmaf(f.w, g.w, s);
    }
#pragma unroll
    for (int o = 16; o; o >>= 1) s += __shfl_xor_sync(0xFFFFFFFFu, s, o);
    if (lane == 0) {
        float z = s + bg[0];
        out[row] = z >= 0.f ? z : 0.01f * z;
    }
}

// ---------------------------------------------------------------------------
template <typename T>
static T* sym_p(const void* s)
{
    void* p = nullptr;
    cudaGetSymbolAddress(&p, s);
    return (T*)p;
}

extern "C" void kernel_launch(void* const* d_in, const int* in_sizes, int n_in,
                              void* d_out, int out_size)
{
    const float* x  = (const float*)d_in[0];
    const float* W1 = (const float*)d_in[2];
    const float* a1 = (const float*)d_in[3];
    const float* W2 = (const float*)d_in[4];
    const float* a2 = (const float*)d_in[5];
    const float* Wg = (const float*)d_in[6];
    const float* bg = (const float*)d_in[7];

    float* out = (float*)d_out;
    float* fc2 = out + (long long)B_ * NN;
    float* g2  = fc2 + (long long)B_ * NN * NN;

    float* h1   = sym_p<float>(d_h1);
    float* g1   = sym_p<float>(d_g1);
    float* h2   = sym_p<float>(d_h2);
    float* el   = sym_p<float>(d_el);
    float* er   = sym_p<float>(d_er);
    float* stat = sym_p<float>(d_stat);
    float* gv   = sym_p<float>(d_gv);
    __nv_bfloat16* ht1h = sym_p<__nv_bfloat16>(d_ht1_hi);
    __nv_bfloat16* ht1l = sym_p<__nv_bfloat16>(d_ht1_lo);
    __nv_bfloat16* ht2h = sym_p<__nv_bfloat16>(d_ht2_hi);
    __nv_bfloat16* ht2l = sym_p<__nv_bfloat16>(d_ht2_lo);
    __nv_bfloat16* wt1h = sym_p<__nv_bfloat16>(d_wt1_hi);
    __nv_bfloat16* wt1l = sym_p<__nv_bfloat16>(d_wt1_lo);
    __nv_bfloat16* wt2h = sym_p<__nv_bfloat16>(d_wt2_hi);
    __nv_bfloat16* wt2l = sym_p<__nv_bfloat16>(d_wt2_lo);

    const int SMB = 2 * 65536;   // 128 KB dynamic smem
    cudaFuncSetAttribute(tc_gemm<0, 0>, cudaFuncAttributeMaxDynamicSharedMemorySize, SMB);
    cudaFuncSetAttribute(tc_gemm<1, 1>, cudaFuncAttributeMaxDynamicSharedMemorySize, SMB);
    cudaFuncSetAttribute(tc_gemm<2, 0>, cudaFuncAttributeMaxDynamicSharedMemorySize, SMB);

    const int rowsTot = B_ * NN;              // 32768
    const dim3 tp(32, 8);

    // ===== weight preps (tiny) =====
    prepT<<<dim3(H1_ / 32, FIN / 32, 1), tp>>>(W1, wt1h, wt1l, FIN, H1_, 0, 0);
    prepT<<<dim3(H2_ / 32, H1_ / 32, 1), tp>>>(W2, wt2h, wt2l, H1_, H2_, 0, 0);

    // ===== Layer 1 =====
    // h1 = x @ W1
    tc_gemm<0, 0><<<dim3(H1_ / 128, rowsTot / 128, 1), 256, SMB>>>(
        x, wt1h, wt1l, h1, H1_, FIN, 0, 0, 0, nullptr, nullptr, nullptr, nullptr);
    rowdot<<<rowsTot / 8, 256>>>(h1, a1, el, er, H1_);
    minmax_stats<<<B_, 256>>>(el, er, stat);
    prepT<<<dim3(H1_ / 32, NN / 32, B_), tp>>>(
        h1, ht1h, ht1l, NN, H1_, (long long)NN * H1_, (long long)H1_ * NN);
    // g1 = elu(att1 @ h1), att1 on the fly
    tc_gemm<1, 1><<<dim3(H1_ / 128, NN / 128, B_), 256, SMB>>>(
        nullptr, ht1h, ht1l, g1, H1_, NN,
        0, (long long)H1_ * NN, (long long)NN * H1_, el, er, stat, nullptr);

    // ===== Layer 2 =====
    tc_gemm<0, 0><<<dim3(H2_ / 128, rowsTot / 128, 1), 256, SMB>>>(
        g1, wt2h, wt2l, h2, H2_, H1_, 0, 0, 0, nullptr, nullptr, nullptr, nullptr);
    rowdot<<<rowsTot / 8, 256>>>(h2, a2, el, er, H2_);
    minmax_stats<<<B_, 256>>>(el, er, stat);
    prepT<<<dim3(H2_ / 32, NN / 32, B_), tp>>>(
        h2, ht2h, ht2l, NN, H2_, (long long)NN * H2_, (long long)H2_ * NN);
    // g2 = fc2 @ h2; fc2 written on the fly (gridDim.x == 1)
    tc_gemm<2, 0><<<dim3(H2_ / 128, NN / 128, B_), 256, SMB>>>(
        nullptr, ht2h, ht2l, g2, H2_, NN,
        0, (long long)H2_ * NN, (long long)NN * H2_, el, er, stat, fc2);

    // ===== Head: out = leaky(fc2 @ (g2 @ Wg) + bg) =====
    gv_kernel<<<rowsTot / 8, 256>>>(g2, Wg, gv);
    z_kernel<<<rowsTot / 8, 256>>>(fc2, gv, bg, out);
}

// round 9
// speedup vs baseline: 2.8503x; 1.3654x over previous
#include <cuda_runtime.h>
#include <cuda_bf16.h>
#include <math.h>
#include <stdint.h>

#define B_   32
#define NN   1024
#define FIN  512
#define H1_  256
#define H2_  128

// ---------------- scratch (device globals; no allocation allowed) ----------
__device__ float d_h1[B_ * NN * H1_];
__device__ float d_g1[B_ * NN * H1_];
__device__ float d_h2[B_ * NN * H2_];
__device__ float d_el[B_ * NN];
__device__ float d_er[B_ * NN];
__device__ float d_stat[B_ * 2];
__device__ float d_gv[B_ * NN];
// transposed + bf16-split B operands ([N][K] layout)
__device__ __nv_bfloat16 d_ht1_hi[B_ * H1_ * NN];
__device__ __nv_bfloat16 d_ht1_lo[B_ * H1_ * NN];
__device__ __nv_bfloat16 d_ht2_hi[B_ * H2_ * NN];
__device__ __nv_bfloat16 d_ht2_lo[B_ * H2_ * NN];
__device__ __nv_bfloat16 d_wt1_hi[H1_ * FIN];
__device__ __nv_bfloat16 d_wt1_lo[H1_ * FIN];
__device__ __nv_bfloat16 d_wt2_hi[H2_ * H1_];
__device__ __nv_bfloat16 d_wt2_lo[H2_ * H1_];

__device__ __forceinline__ uint32_t smem_u32(const void* p) {
    return (uint32_t)__cvta_generic_to_shared(p);
}
__device__ __forceinline__ uint32_t sw64(uint32_t off) {
    return off ^ ((off >> 3) & 0x30);
}
__device__ __forceinline__ float attf(float x, float mn, float kk) {
    float lr = x >= 0.f ? x : 0.01f * x;
    return 1.f / (1.f + __expf(-(fmaf(lr - mn, kk, -20.f))));
}
__device__ __forceinline__ void ldx4(unsigned* r, uint32_t addr) {
    asm volatile("ldmatrix.sync.aligned.m8n8.x4.shared.b16 {%0,%1,%2,%3}, [%4];"
                 : "=r"(r[0]), "=r"(r[1]), "=r"(r[2]), "=r"(r[3]) : "r"(addr));
}
__device__ __forceinline__ void ldx2(unsigned* r, uint32_t addr) {
    asm volatile("ldmatrix.sync.aligned.m8n8.x2.shared.b16 {%0,%1}, [%2];"
                 : "=r"(r[0]), "=r"(r[1]) : "r"(addr));
}
__device__ __forceinline__ void mma16816(float* c, const unsigned* a, const unsigned* b) {
    asm volatile(
        "mma.sync.aligned.m16n8k16.row.col.f32.bf16.bf16.f32 "
        "{%0,%1,%2,%3}, {%4,%5,%6,%7}, {%8,%9}, {%0,%1,%2,%3};"
        : "+f"(c[0]), "+f"(c[1]), "+f"(c[2]), "+f"(c[3])
        : "r"(a[0]), "r"(a[1]), "r"(a[2]), "r"(a[3]), "r"(b[0]), "r"(b[1]));
}
__device__ __forceinline__ void cpasync16(uint32_t saddr, const void* gptr) {
    asm volatile("cp.async.cg.shared.global [%0], [%1], 16;"
                 :: "r"(saddr), "l"(gptr) : "memory");
}
#define CP_COMMIT() asm volatile("cp.async.commit_group;" ::: "memory")
#define CP_WAIT0()  asm volatile("cp.async.wait_group 0;" ::: "memory")

// ---------------- tensor-core GEMM: C[M,N] = A[M,K] @ Bt^T -------------------
// A: [M,K] fp32 (MODE 0) or att(el,er,stat) on the fly (MODE 1; MODE 2 also
// writes fp32 att to attOut — requires gridDim.x == 1). Bt: bf16 hi/lo [N][K].
// CTA tile 128x128, BK=32, 8 warps (2m x 4n), warp tile 64x32, m16n8k16.
// bf16x3: hi*hi + lo*hi + hi*lo. EPI: 0 none, 1 ELU. 2 CTAs/SM, SW64 smem.
template <int MODE, int EPI>
__global__ void __launch_bounds__(256, 2)
tc_gemm(const float* __restrict__ A,
        const __nv_bfloat16* __restrict__ Bhi, const __nv_bfloat16* __restrict__ Blo,
        float* __restrict__ C, int N, int K,
        long long sA, long long sBt, long long sC,
        const float* __restrict__ el, const float* __restrict__ er,
        const float* __restrict__ stat, float* __restrict__ attOut)
{
    extern __shared__ char smem[];
    // per buffer: A_hi 8K | A_lo 8K | B_hi 8K | B_lo 8K = 32K; two buffers
    constexpr int BUF = 32768;
    constexpr int OAH = 0, OAL = 8192, OBH = 16384, OBL = 24576;

    const int bz = blockIdx.z;
    if (MODE == 0) A += (long long)bz * sA;
    Bhi += (long long)bz * sBt;
    Blo += (long long)bz * sBt;
    C   += (long long)bz * sC;

    const int m0 = blockIdx.y * 128;
    const int n0 = blockIdx.x * 128;
    const int tid  = threadIdx.x;
    const int warp = tid >> 5, lane = tid & 31;
    const int mw = (warp >> 2) * 64;     // warp row base in tile
    const int nw = (warp & 3) * 32;      // warp col base in tile

    const uint32_t sb = smem_u32(smem);

    // A producer mapping: row = tid>>1 (0..127), 16-col half (tid&1)
    const int ar = tid >> 1;
    const int ac = (tid & 1) * 16;
    float elv = 0.f, mn = 0.f, kk = 0.f;
    if (MODE != 0) {
        elv = el[bz * NN + m0 + ar];
        mn  = stat[bz * 2 + 0];
        kk  = stat[bz * 2 + 1];
    }

    float va[16];

    // ---- load A-source for chunk c into registers (pure LDG) ----
    auto produce_load = [&](int c) {
        const int k0 = c << 5;
        const float4* Sp = (MODE == 0)
            ? (const float4*)(A + (long long)(m0 + ar) * K + k0 + ac)
            : (const float4*)(er + bz * NN + k0 + ac);
#pragma unroll
        for (int q = 0; q < 4; q++) {
            float4 f = Sp[q];
            va[q * 4 + 0] = f.x; va[q * 4 + 1] = f.y;
            va[q * 4 + 2] = f.z; va[q * 4 + 3] = f.w;
        }
    };

    // ---- B planes straight to smem via cp.async ----
    auto produce_B = [&](int c, int buf) {
        const int k0 = c << 5;
        const uint32_t dH = sb + buf * BUF + OBH;
        const uint32_t dL = sb + buf * BUF + OBL;
#pragma unroll
        for (int rep = 0; rep < 2; rep++) {
            int idx = tid + rep * 256;         // 0..511 granules per plane
            int row = idx >> 2, q = idx & 3;
            uint32_t so = sw64(row * 64 + q * 16);
            cpasync16(dH + so, Bhi + (long long)(n0 + row) * K + k0 + q * 8);
            cpasync16(dL + so, Blo + (long long)(n0 + row) * K + k0 + q * 8);
        }
        CP_COMMIT();
    };

    // ---- finish A: attf (MODE!=0), split to hi/lo, STS (+ STG att, MODE 2) --
    auto produce_store = [&](int c, int buf) {
        char* base = smem + buf * BUF;
        if (MODE != 0) {
#pragma unroll
            for (int e = 0; e < 16; e++) va[e] = attf(elv + va[e], mn, kk);
            if (MODE == 2) {
                const int k0 = c << 5;
                float4* Op = (float4*)(attOut + (long long)bz * NN * NN +
                                       (long long)(m0 + ar) * NN + k0 + ac);
#pragma unroll
                for (int q = 0; q < 4; q++)
                    Op[q] = make_float4(va[q * 4], va[q * 4 + 1], va[q * 4 + 2], va[q * 4 + 3]);
            }
        }
#pragma unroll
        for (int g = 0; g < 2; g++) {
            uint4 hq, lq;
            uint32_t* hw = (uint32_t*)&hq;
            uint32_t* lw = (uint32_t*)&lq;
#pragma unroll
            for (int e = 0; e < 4; e++) {
                float x0 = va[g * 8 + e * 2], x1 = va[g * 8 + e * 2 + 1];
                __nv_bfloat16 h0 = __float2bfloat16(x0), h1 = __float2bfloat16(x1);
                float r0 = x0 - __bfloat162float(h0);
                float r1 = x1 - __bfloat162float(h1);
                __nv_bfloat16 l0 = __float2bfloat16(r0), l1 = __float2bfloat16(r1);
                hw[e] = (uint32_t)__bfloat16_as_ushort(h0) |
                        ((uint32_t)__bfloat16_as_ushort(h1) << 16);
                lw[e] = (uint32_t)__bfloat16_as_ushort(l0) |
                        ((uint32_t)__bfloat16_as_ushort(l1) << 16);
            }
            uint32_t so = sw64(ar * 64 + ac * 2 + g * 16);
            *(uint4*)(base + OAH + so) = hq;
            *(uint4*)(base + OAL + so) = lq;
        }
    };

    float acc[4][4][4] = {};

    auto consume = [&](int buf) {
        const uint32_t aH = sb + buf * BUF + OAH;
        const uint32_t aL = sb + buf * BUF + OAL;
        const uint32_t bH = sb + buf * BUF + OBH;
        const uint32_t bL = sb + buf * BUF + OBL;
        const uint32_t aRow = (lane & 15);
        const uint32_t aKof = (lane >> 4) * 16;
        const uint32_t bRow = (lane & 7);
        const uint32_t bKof = ((lane >> 3) & 1) * 16;
#pragma unroll
        for (int ks = 0; ks < 2; ks++) {
            const uint32_t kb = ks * 32;       // byte col of k0+ks*16
            unsigned ah[4][4], al[4][4], bh[4][2], bl[4][2];
#pragma unroll
            for (int mt = 0; mt < 4; mt++) {
                uint32_t off = sw64((mw + mt * 16 + aRow) * 64 + kb + aKof);
                ldx4(ah[mt], aH + off);
                ldx4(al[mt], aL + off);
            }
#pragma unroll
            for (int nt = 0; nt < 4; nt++) {
                uint32_t off = sw64((nw + nt * 8 + bRow) * 64 + kb + bKof);
                ldx2(bh[nt], bH + off);
                ldx2(bl[nt], bL + off);
            }
#pragma unroll
            for (int mt = 0; mt < 4; mt++) {
#pragma unroll
                for (int nt = 0; nt < 4; nt++) {
                    mma16816(acc[mt][nt], ah[mt], bh[nt]);
                    mma16816(acc[mt][nt], al[mt], bh[nt]);
                    mma16816(acc[mt][nt], ah[mt], bl[nt]);
                }
            }
        }
    };

    const int nCh = K >> 5;
    // prologue
    produce_load(0);
    produce_B(0, 0);
    produce_store(0, 0);
    CP_WAIT0();
    __syncthreads();

    int buf = 0;
    for (int c = 0; c < nCh; c++) {
        const bool more = (c + 1 < nCh);
        if (more) {
            produce_load(c + 1);       // LDG issued; latency covered by consume
            produce_B(c + 1, buf ^ 1); // cp.async, off-thread
        }
        consume(buf);
        if (more) produce_store(c + 1, buf ^ 1);
        CP_WAIT0();
        __syncthreads();
        buf ^= 1;
    }

    // ---- epilogue: fragment -> global ----
    const int r0 = lane >> 2;
    const int cc = (lane & 3) * 2;
#pragma unroll
    for (int mt = 0; mt < 4; mt++) {
#pragma unroll
        for (int nt = 0; nt < 4; nt++) {
            float* a4 = acc[mt][nt];
            if (EPI == 1) {
#pragma unroll
                for (int e = 0; e < 4; e++)
                    a4[e] = a4[e] > 0.f ? a4[e] : (__expf(a4[e]) - 1.f);
            }
            const int col = n0 + nw + nt * 8 + cc;
            const int row = m0 + mw + mt * 16 + r0;
            *(float2*)&C[(long long)row * N + col]       = make_float2(a4[0], a4[1]);
            *(float2*)&C[(long long)(row + 8) * N + col] = make_float2(a4[2], a4[3]);
        }
    }
}

// ---------------- transpose + bf16 split: dst[c][r] = split(src[r][c]) ------
__global__ void prepT(const float* __restrict__ src, __nv_bfloat16* __restrict__ dhi,
                      __nv_bfloat16* __restrict__ dlo, int R, int Cc,
                      long long sS, long long sD)
{
    __shared__ float t[32][33];
    const int bz = blockIdx.z;
    src += (long long)bz * sS;
    dhi += (long long)bz * sD;
    dlo += (long long)bz * sD;
    const int c0 = blockIdx.x * 32;
    const int r0 = blockIdx.y * 32;
    const int tx = threadIdx.x, ty = threadIdx.y;
#pragma unroll
    for (int i = ty; i < 32; i += 8)
        t[i][tx] = src[(long long)(r0 + i) * Cc + c0 + tx];
    __syncthreads();
#pragma unroll
    for (int i = ty; i < 32; i += 8) {
        float v = t[tx][i];
        __nv_bfloat16 h = __float2bfloat16(v);
        float rr = v - __bfloat162float(h);
        dhi[(long long)(c0 + i) * R + r0 + tx] = h;
        dlo[(long long)(c0 + i) * R + r0 + tx] = __float2bfloat16(rr);
    }
}

// ---------------- per-row dual dot: el = h.aL, er = h.aR --------------------
__global__ void rowdot(const float* __restrict__ h, const float* __restrict__ a,
                       float* __restrict__ el, float* __restrict__ er, int Fo)
{
    const int row  = (blockIdx.x * blockDim.x + threadIdx.x) >> 5;
    const int lane = threadIdx.x & 31;
    const float* hp = h + (long long)row * Fo;
    float sl = 0.f, sr = 0.f;
    for (int c = lane; c < Fo; c += 32) {
        float v = hp[c];
        sl = fmaf(v, a[c], sl);
        sr = fmaf(v, a[Fo + c], sr);
    }
#pragma unroll
    for (int o = 16; o; o >>= 1) {
        sl += __shfl_xor_sync(0xFFFFFFFFu, sl, o);
        sr += __shfl_xor_sync(0xFFFFFFFFu, sr, o);
    }
    if (lane == 0) { el[row] = sl; er[row] = sr; }
}

// ---------------- per-batch min/max of separable e --------------------------
__global__ void minmax_stats(const float* __restrict__ el, const float* __restrict__ er,
                             float* __restrict__ stat)
{
    const int b = blockIdx.x;
    const int tid = threadIdx.x;
    float mnl = 1e30f, mxl = -1e30f, mnr = 1e30f, mxr = -1e30f;
    for (int i = tid; i < NN; i += 256) {
        float l = el[b * NN + i], r = er[b * NN + i];
        mnl = fminf(mnl, l); mxl = fmaxf(mxl, l);
        mnr = fminf(mnr, r); mxr = fmaxf(mxr, r);
    }
#pragma unroll
    for (int o = 16; o; o >>= 1) {
        mnl = fminf(mnl, __shfl_xor_sync(0xFFFFFFFFu, mnl, o));
        mxl = fmaxf(mxl, __shfl_xor_sync(0xFFFFFFFFu, mxl, o));
        mnr = fminf(mnr, __shfl_xor_sync(0xFFFFFFFFu, mnr, o));
        mxr = fmaxf(mxr, __shfl_xor_sync(0xFFFFFFFFu, mxr, o));
    }
    __shared__ float s[4][8];
    const int w = tid >> 5, lane = tid & 31;
    if (lane == 0) { s[0][w] = mnl; s[1][w] = mxl; s[2][w] = mnr; s[3][w] = mxr; }
    __syncthreads();
    if (tid == 0) {
        float a0 = s[0][0], a1 = s[1][0], a2 = s[2][0], a3 = s[3][0];
#pragma unroll
        for (int i = 1; i < 8; i++) {
            a0 = fminf(a0, s[0][i]); a1 = fmaxf(a1, s[1][i]);
            a2 = fminf(a2, s[2][i]); a3 = fmaxf(a3, s[3][i]);
        }
        float lo = a0 + a2, hi = a1 + a3;
        float mn = lo >= 0.f ? lo : 0.01f * lo;
        float mx = hi >= 0.f ? hi : 0.01f * hi;
        stat[b * 2 + 0] = mn;
        stat[b * 2 + 1] = 30.f / (mx - mn);
    }
}

// ---------------- gv = g2 @ Wg ----------------------------------------------
__global__ void gv_kernel(const float* __restrict__ g2, const float* __restrict__ Wg,
                          float* __restrict__ gv)
{
    const int row  = (blockIdx.x * blockDim.x + threadIdx.x) >> 5;
    const int lane = threadIdx.x & 31;
    const float* gp = g2 + (long long)row * H2_;
    float s = fmaf(gp[lane], Wg[lane], gp[lane + 32] * Wg[lane + 32]);
    s = fmaf(gp[lane + 64], Wg[lane + 64], s);
    s = fmaf(gp[lane + 96], Wg[lane + 96], s);
#pragma unroll
    for (int o = 16; o; o >>= 1) s += __shfl_xor_sync(0xFFFFFFFFu, s, o);
    if (lane == 0) gv[row] = s;
}

// ---------------- out = leaky(fc2 @ gv + bg) ----------------------------------
__global__ void z_kernel(const float* __restrict__ fc2, const float* __restrict__ gv,
                         const float* __restrict__ bg, float* __restrict__ out)
{
    const int row  = (blockIdx.x * blockDim.x + threadIdx.x) >> 5;
    const int lane = threadIdx.x & 31;
    const int b = row >> 10;
    const float* fr = fc2 + (long long)row * NN;
    const float* gr = gv + b * NN;
    float s = 0.f;
#pragma unroll
    for (int j = lane * 4; j < NN; j += 128) {
        float4 f = *(const float4*)&fr[j];
        float4 g = *(const float4*)&gr[j];
        s = fmaf(f.x, g.x, s); s = fmaf(f.y, g.y, s);
        s = fmaf(f.z, g.z, s); s = fmaf(f.w, g.w, s);
    }
#pragma unroll
    for (int o = 16; o; o >>= 1) s += __shfl_xor_sync(0xFFFFFFFFu, s, o);
    if (lane == 0) {
        float z = s + bg[0];
        out[row] = z >= 0.f ? z : 0.01f * z;
    }
}

// ---------------------------------------------------------------------------
template <typename T>
static T* sym_p(const void* s)
{
    void* p = nullptr;
    cudaGetSymbolAddress(&p, s);
    return (T*)p;
}

extern "C" void kernel_launch(void* const* d_in, const int* in_sizes, int n_in,
                              void* d_out, int out_size)
{
    const float* x  = (const float*)d_in[0];
    const float* W1 = (const float*)d_in[2];
    const float* a1 = (const float*)d_in[3];
    const float* W2 = (const float*)d_in[4];
    const float* a2 = (const float*)d_in[5];
    const float* Wg = (const float*)d_in[6];
    const float* bg = (const float*)d_in[7];

    float* out = (float*)d_out;
    float* fc2 = out + (long long)B_ * NN;
    float* g2  = fc2 + (long long)B_ * NN * NN;

    float* h1   = sym_p<float>(d_h1);
    float* g1   = sym_p<float>(d_g1);
    float* h2   = sym_p<float>(d_h2);
    float* el   = sym_p<float>(d_el);
    float* er   = sym_p<float>(d_er);
    float* stat = sym_p<float>(d_stat);
    float* gv   = sym_p<float>(d_gv);
    __nv_bfloat16* ht1h = sym_p<__nv_bfloat16>(d_ht1_hi);
    __nv_bfloat16* ht1l = sym_p<__nv_bfloat16>(d_ht1_lo);
    __nv_bfloat16* ht2h = sym_p<__nv_bfloat16>(d_ht2_hi);
    __nv_bfloat16* ht2l = sym_p<__nv_bfloat16>(d_ht2_lo);
    __nv_bfloat16* wt1h = sym_p<__nv_bfloat16>(d_wt1_hi);
    __nv_bfloat16* wt1l = sym_p<__nv_bfloat16>(d_wt1_lo);
    __nv_bfloat16* wt2h = sym_p<__nv_bfloat16>(d_wt2_hi);
    __nv_bfloat16* wt2l = sym_p<__nv_bfloat16>(d_wt2_lo);

    const int SMB = 2 * 32768;   // 64 KB dynamic smem per CTA
    cudaFuncSetAttribute(tc_gemm<0, 0>, cudaFuncAttributeMaxDynamicSharedMemorySize, SMB);
    cudaFuncSetAttribute(tc_gemm<1, 1>, cudaFuncAttributeMaxDynamicSharedMemorySize, SMB);
    cudaFuncSetAttribute(tc_gemm<2, 0>, cudaFuncAttributeMaxDynamicSharedMemorySize, SMB);

    const int rowsTot = B_ * NN;              // 32768
    const dim3 tp(32, 8);

    // ===== weight preps (tiny) =====
    prepT<<<dim3(H1_ / 32, FIN / 32, 1), tp>>>(W1, wt1h, wt1l, FIN, H1_, 0, 0);
    prepT<<<dim3(H2_ / 32, H1_ / 32, 1), tp>>>(W2, wt2h, wt2l, H1_, H2_, 0, 0);

    // ===== Layer 1 =====
    // h1 = x @ W1
    tc_gemm<0, 0><<<dim3(H1_ / 128, rowsTot / 128, 1), 256, SMB>>>(
        x, wt1h, wt1l, h1, H1_, FIN, 0, 0, 0, nullptr, nullptr, nullptr, nullptr);
    rowdot<<<rowsTot / 8, 256>>>(h1, a1, el, er, H1_);
    minmax_stats<<<B_, 256>>>(el, er, stat);
    prepT<<<dim3(H1_ / 32, NN / 32, B_), tp>>>(
        h1, ht1h, ht1l, NN, H1_, (long long)NN * H1_, (long long)H1_ * NN);
    // g1 = elu(att1 @ h1), att1 on the fly
    tc_gemm<1, 1><<<dim3(H1_ / 128, NN / 128, B_), 256, SMB>>>(
        nullptr, ht1h, ht1l, g1, H1_, NN,
        0, (long long)H1_ * NN, (long long)NN * H1_, el, er, stat, nullptr);

    // ===== Layer 2 =====
    tc_gemm<0, 0><<<dim3(H2_ / 128, rowsTot / 128, 1), 256, SMB>>>(
        g1, wt2h, wt2l, h2, H2_, H1_, 0, 0, 0, nullptr, nullptr, nullptr, nullptr);
    rowdot<<<rowsTot / 8, 256>>>(h2, a2, el, er, H2_);
    minmax_stats<<<B_, 256>>>(el, er, stat);
    prepT<<<dim3(H2_ / 32, NN / 32, B_), tp>>>(
        h2, ht2h, ht2l, NN, H2_, (long long)NN * H2_, (long long)H2_ * NN);
    // g2 = fc2 @ h2; fc2 written on the fly (gridDim.x == 1)
    tc_gemm<2, 0><<<dim3(H2_ / 128, NN / 128, B_), 256, SMB>>>(
        nullptr, ht2h, ht2l, g2, H2_, NN,
        0, (long long)H2_ * NN, (long long)NN * H2_, el, er, stat, fc2);

    // ===== Head: out = leaky(fc2 @ (g2 @ Wg) + bg) =====
    gv_kernel<<<rowsTot / 8, 256>>>(g2, Wg, gv);
    z_kernel<<<rowsTot / 8, 256>>>(fc2, gv, bg, out);
}